// round 11
// baseline (speedup 1.0000x reference)
#include <cuda_runtime.h>
#include <cuda_fp16.h>
#include <cstdint>
#include <cstddef>

// ---------------- problem constants ----------------
#define TOK 16384
#define HD  2048
#define ID  4096
#define NG  4

// ---------------- device scratch ----------------
__device__ __half g_bufA[(size_t)TOK * ID];
__device__ __half g_bufB[(size_t)TOK * ID];
__device__ __half g_w1h [(size_t)ID * HD];
__device__ __half g_w2h [(size_t)HD * ID];
__device__ __half g_l0g1[(size_t)NG * ID * HD];
__device__ __half g_l0g2[(size_t)NG * HD * ID];
__device__ __half g_l1g1[(size_t)NG * ID * HD];
__device__ __half g_l1g2[(size_t)NG * HD * ID];

// ---------------- fused fp32 -> fp16 conversion (single launch) ----------------
struct ConvJobs {
    const float4* src[7];
    __half2*      dst[7];
    unsigned long long off[8];   // prefix offsets in float4 units
};

__global__ __launch_bounds__(256)
void f2h_fused_kernel(ConvJobs jobs) {
    unsigned long long i = (unsigned long long)blockIdx.x * blockDim.x + threadIdx.x;
    if (i >= jobs.off[7]) return;
#pragma unroll
    for (int j = 0; j < 7; ++j) {
        if (i < jobs.off[j + 1]) {
            unsigned long long r = i - jobs.off[j];
            float4 v = jobs.src[j][r];
            jobs.dst[j][2 * r]     = __floats2half2_rn(v.x, v.y);
            jobs.dst[j][2 * r + 1] = __floats2half2_rn(v.z, v.w);
            return;
        }
    }
}

// ---------------- tile config ----------------
constexpr int BM = 128, BN = 128, BK = 64;
constexpr int STAGES = 3;
constexpr int ASTG = BM * 128;              // 16384 B
constexpr int BSTG = BN * 128;              // 16384 B
constexpr int STG  = ASTG + BSTG;           // 32768 B per stage
constexpr int SMEM_BYTES = STAGES * STG;    // 98304 B -> 2 CTAs / SM

// ---------------- helpers ----------------
__device__ __forceinline__ uint32_t smem_u32(const void* p) {
    return (uint32_t)__cvta_generic_to_shared(p);
}
__device__ __forceinline__ uint32_t swz(uint32_t off) {   // SW128-style XOR swizzle
    return off ^ ((off >> 3) & 0x70);
}
__device__ __forceinline__ void cp16(uint32_t dst, const void* src) {
    asm volatile("cp.async.cg.shared.global [%0], [%1], 16;\n" :: "r"(dst), "l"(src));
}
__device__ __forceinline__ void cp_commit() { asm volatile("cp.async.commit_group;\n"); }
template <int N>
__device__ __forceinline__ void cp_wait() { asm volatile("cp.async.wait_group %0;\n" :: "n"(N)); }

__device__ __forceinline__ void ldsm_x4(uint32_t* r, uint32_t addr) {
    asm volatile("ldmatrix.sync.aligned.m8n8.x4.shared.b16 {%0,%1,%2,%3}, [%4];\n"
                 : "=r"(r[0]), "=r"(r[1]), "=r"(r[2]), "=r"(r[3]) : "r"(addr));
}
__device__ __forceinline__ void mma16816(float* c, const uint32_t* a, const uint32_t* b) {
    asm volatile("mma.sync.aligned.m16n8k16.row.col.f32.f16.f16.f32 "
                 "{%0,%1,%2,%3}, {%4,%5,%6,%7}, {%8,%9}, {%0,%1,%2,%3};\n"
                 : "+f"(c[0]), "+f"(c[1]), "+f"(c[2]), "+f"(c[3])
                 : "r"(a[0]), "r"(a[1]), "r"(a[2]), "r"(a[3]), "r"(b[0]), "r"(b[1]));
}

// ---------------- fp16 GEMM:  C[M,N] = A[M,K] * W[N,K]^T + bias ----------------
// grid = (N/BN, M/BM). Grouped along M: group = bm / mRowsPerGroup.
// 8 warps, warp tile 64x32, register double-buffered fragments, 2 CTAs/SM.
template <typename OutT>
__global__ __launch_bounds__(256, 2)
void gemm_kernel(const __half* __restrict__ A, const __half* __restrict__ W,
                 const float* __restrict__ bias, OutT* __restrict__ C,
                 int N, int K, int mRowsPerGroup) {
    extern __shared__ char smem_raw[];
    const uint32_t sbase = smem_u32(smem_raw);

    const int tid  = threadIdx.x;
    const int lane = tid & 31;
    const int warp = tid >> 5;
    const int wm   = warp >> 2;   // 2 x 64 rows
    const int wn   = warp & 3;    // 4 x 32 cols
    const int bm   = blockIdx.y * BM;
    const int bn   = blockIdx.x * BN;
    const int group = bm / mRowsPerGroup;

    const __half* gA = A + (size_t)bm * K;
    const __half* gW = W + (size_t)group * N * K + (size_t)bn * K;
    const float*  gBias = bias + (size_t)group * N + bn;
    const int kTiles = K / BK;

    // per-lane UNswizzled LDSM base offsets. Low field uses only bits <=4
    // (c*2 in {0,16}); ks adds 32*ks (bits 5-6) -> carry-free add, then swizzle.
    uint32_t aOff[4], bOff[2];
#pragma unroll
    for (int mi = 0; mi < 4; ++mi) {
        int r = wm * 64 + mi * 16 + (lane & 15);
        int c = (lane >> 4) * 8;
        aOff[mi] = (uint32_t)(r * 128 + c * 2);
    }
#pragma unroll
    for (int np = 0; np < 2; ++np) {
        int r = wn * 32 + np * 16 + ((lane >> 4) & 1) * 8 + (lane & 7);
        int c = ((lane >> 3) & 1) * 8;
        bOff[np] = (uint32_t)(r * 128 + c * 2);
    }

    float acc[4][4][4];
#pragma unroll
    for (int a = 0; a < 4; a++)
#pragma unroll
        for (int b = 0; b < 4; b++)
#pragma unroll
            for (int c = 0; c < 4; c++) acc[a][b][c] = 0.f;

    auto load_stage = [&](int s, int kt) {
        const uint32_t dA = sbase + s * STG;
        const uint32_t dB = dA + ASTG;
        const __half* srcA = gA + kt * BK;
        const __half* srcB = gW + kt * BK;
#pragma unroll
        for (int i = 0; i < 4; i++) {       // A: 1024 chunks of 16B
            int q = tid + i * 256;
            int r = q >> 3, c = q & 7;
            cp16(dA + swz((uint32_t)(r * 128 + c * 16)), srcA + (size_t)r * K + c * 8);
        }
#pragma unroll
        for (int i = 0; i < 4; i++) {       // B: 1024 chunks of 16B
            int q = tid + i * 256;
            int r = q >> 3, c = q & 7;
            cp16(dB + swz((uint32_t)(r * 128 + c * 16)), srcB + (size_t)r * K + c * 8);
        }
    };

    uint32_t aF[2][4][4], bF[2][4][2];
    auto load_frags = [&](int buf, uint32_t cA, uint32_t cB, int ks) {
        const uint32_t kOff = (uint32_t)(ks * 32);
#pragma unroll
        for (int mi = 0; mi < 4; ++mi)
            ldsm_x4(aF[buf][mi], cA + swz(aOff[mi] + kOff));
#pragma unroll
        for (int np = 0; np < 2; ++np) {
            uint32_t t[4];
            ldsm_x4(t, cB + swz(bOff[np] + kOff));
            bF[buf][2 * np][0] = t[0]; bF[buf][2 * np][1] = t[1];
            bF[buf][2 * np + 1][0] = t[2]; bF[buf][2 * np + 1][1] = t[3];
        }
    };

    // prologue: 2 stages in flight
    load_stage(0, 0); cp_commit();
    if (kTiles > 1) load_stage(1, 1);
    cp_commit();

    for (int kt = 0; kt < kTiles; ++kt) {
        cp_wait<1>();          // stage kt resident
        __syncthreads();       // all warps done with stage (kt-1)

        const uint32_t cA = sbase + (kt % STAGES) * STG;
        const uint32_t cB = cA + ASTG;

        // first fragments ASAP to shorten the post-barrier dependency wall
        load_frags(0, cA, cB, 0);

        // then issue next-stage cp.async so it overlaps all MMAs below
        const int nk = kt + 2;
        if (nk < kTiles) load_stage(nk % STAGES, nk);
        cp_commit();

#pragma unroll
        for (int ks = 0; ks < BK / 16; ++ks) {
            const int cur = ks & 1;
            if (ks < BK / 16 - 1)
                load_frags(cur ^ 1, cA, cB, ks + 1);   // prefetch next ks
#pragma unroll
            for (int mi = 0; mi < 4; ++mi)
#pragma unroll
                for (int ni = 0; ni < 4; ++ni)
                    mma16816(acc[mi][ni], aF[cur][mi], bF[cur][ni]);
        }
    }

    // ---------------- epilogue: bias add + store ----------------
#pragma unroll
    for (int mi = 0; mi < 4; ++mi) {
#pragma unroll
        for (int ni = 0; ni < 4; ++ni) {
            int r0 = bm + wm * 64 + mi * 16 + (lane >> 2);
            int cb = wn * 32 + ni * 8 + (lane & 3) * 2;
            int c0 = bn + cb;
            float bv0 = gBias[cb], bv1 = gBias[cb + 1];
            float v0 = acc[mi][ni][0] + bv0;
            float v1 = acc[mi][ni][1] + bv1;
            float v2 = acc[mi][ni][2] + bv0;
            float v3 = acc[mi][ni][3] + bv1;
            if constexpr (sizeof(OutT) == 2) {
                *(__half2*)((__half*)C + (size_t)r0 * N + c0)       = __floats2half2_rn(v0, v1);
                *(__half2*)((__half*)C + (size_t)(r0 + 8) * N + c0) = __floats2half2_rn(v2, v3);
            } else {
                *(float2*)((float*)C + (size_t)r0 * N + c0)       = make_float2(v0, v1);
                *(float2*)((float*)C + (size_t)(r0 + 8) * N + c0) = make_float2(v2, v3);
            }
        }
    }
}

// ---------------- host launcher ----------------
static inline void* sym_addr(const void* symbol) {
    void* p = nullptr;
    cudaGetSymbolAddress(&p, symbol);
    return p;
}

extern "C" void kernel_launch(void* const* d_in, const int* in_sizes, int n_in,
                              void* d_out, int out_size) {
    const float* x    = (const float*)d_in[0];
    const float* w1   = (const float*)d_in[1];
    const float* b1   = (const float*)d_in[2];
    const float* w2   = (const float*)d_in[3];
    const float* b2   = (const float*)d_in[4];
    const float* g1w0 = (const float*)d_in[5];
    const float* g1b0 = (const float*)d_in[6];
    const float* g2w0 = (const float*)d_in[7];
    const float* g2b0 = (const float*)d_in[8];
    const float* g1w1 = (const float*)d_in[9];
    const float* g1b1 = (const float*)d_in[10];
    const float* g2w1 = (const float*)d_in[11];
    const float* g2b1 = (const float*)d_in[12];

    __half* bufA = (__half*)sym_addr(g_bufA);
    __half* bufB = (__half*)sym_addr(g_bufB);
    __half* w1h  = (__half*)sym_addr(g_w1h);
    __half* w2h  = (__half*)sym_addr(g_w2h);
    __half* l0g1 = (__half*)sym_addr(g_l0g1);
    __half* l0g2 = (__half*)sym_addr(g_l0g2);
    __half* l1g1 = (__half*)sym_addr(g_l1g1);
    __half* l1g2 = (__half*)sym_addr(g_l1g2);

    cudaFuncSetAttribute(gemm_kernel<__half>, cudaFuncAttributeMaxDynamicSharedMemorySize, SMEM_BYTES);
    cudaFuncSetAttribute(gemm_kernel<float>,  cudaFuncAttributeMaxDynamicSharedMemorySize, SMEM_BYTES);

    // ---- single fused conversion launch ----
    ConvJobs jobs;
    const float* srcs[7] = {x, w1, w2, g1w0, g2w0, g1w1, g2w1};
    __half* dsts[7]      = {bufA, w1h, w2h, l0g1, l0g2, l1g1, l1g2};
    size_t counts[7] = {(size_t)TOK * HD, (size_t)ID * HD, (size_t)HD * ID,
                        (size_t)NG * ID * HD, (size_t)NG * HD * ID,
                        (size_t)NG * ID * HD, (size_t)NG * HD * ID};
    unsigned long long acc = 0;
    for (int j = 0; j < 7; ++j) {
        jobs.src[j] = (const float4*)srcs[j];
        jobs.dst[j] = (__half2*)dsts[j];
        jobs.off[j] = acc;
        acc += counts[j] / 4;
    }
    jobs.off[7] = acc;
    {
        unsigned blocks = (unsigned)((acc + 255) / 256);
        f2h_fused_kernel<<<blocks, 256>>>(jobs);
    }

    dim3 blk(256);
    // stage 1: dense w1  [16384,2048] x [4096,2048]^T -> [16384,4096]
    gemm_kernel<__half><<<dim3(ID / BN, TOK / BM), blk, SMEM_BYTES>>>(bufA, w1h, b1, bufB, ID, HD, TOK);
    // stage 2: dense w2 -> [16384,2048]
    gemm_kernel<__half><<<dim3(HD / BN, TOK / BM), blk, SMEM_BYTES>>>(bufB, w2h, b2, bufA, HD, ID, TOK);
    // layer 0 grouped
    gemm_kernel<__half><<<dim3(ID / BN, TOK / BM), blk, SMEM_BYTES>>>(bufA, l0g1, g1b0, bufB, ID, HD, TOK / NG);
    gemm_kernel<__half><<<dim3(HD / BN, TOK / BM), blk, SMEM_BYTES>>>(bufB, l0g2, g2b0, bufA, HD, ID, TOK / NG);
    // layer 1 grouped
    gemm_kernel<__half><<<dim3(ID / BN, TOK / BM), blk, SMEM_BYTES>>>(bufA, l1g1, g1b1, bufB, ID, HD, TOK / NG);
    // final: fp32 straight to d_out
    gemm_kernel<float><<<dim3(HD / BN, TOK / BM), blk, SMEM_BYTES>>>(bufB, l1g2, g2b1, (float*)d_out, HD, ID, TOK / NG);
}

// round 12
// speedup vs baseline: 1.0661x; 1.0661x over previous
#include <cuda_runtime.h>
#include <cuda_fp16.h>
#include <cstdint>
#include <cstddef>

// ---------------- problem constants ----------------
#define TOK 16384
#define HD  2048
#define ID  4096
#define NG  4

// ---------------- device scratch ----------------
__device__ __half g_bufA[(size_t)TOK * ID];
__device__ __half g_bufB[(size_t)TOK * ID];
__device__ __half g_w1h [(size_t)ID * HD];
__device__ __half g_w2h [(size_t)HD * ID];
__device__ __half g_l0g1[(size_t)NG * ID * HD];
__device__ __half g_l0g2[(size_t)NG * HD * ID];
__device__ __half g_l1g1[(size_t)NG * ID * HD];
__device__ __half g_l1g2[(size_t)NG * HD * ID];

// ---------------- fused fp32 -> fp16 conversion (single launch) ----------------
struct ConvJobs {
    const float4* src[7];
    __half2*      dst[7];
    unsigned long long off[8];   // prefix offsets in float4 units
};

__global__ __launch_bounds__(256)
void f2h_fused_kernel(ConvJobs jobs) {
    unsigned long long i = (unsigned long long)blockIdx.x * blockDim.x + threadIdx.x;
    if (i >= jobs.off[7]) return;
#pragma unroll
    for (int j = 0; j < 7; ++j) {
        if (i < jobs.off[j + 1]) {
            unsigned long long r = i - jobs.off[j];
            float4 v = jobs.src[j][r];
            jobs.dst[j][2 * r]     = __floats2half2_rn(v.x, v.y);
            jobs.dst[j][2 * r + 1] = __floats2half2_rn(v.z, v.w);
            return;
        }
    }
}

// ---------------- tile config ----------------
constexpr int BM = 128, BN = 256, BK = 64;
constexpr int STAGES = 3;
constexpr int ASTG = BM * 128;              // 16384 B
constexpr int BSTG = BN * 128;              // 32768 B
constexpr int STG  = ASTG + BSTG;           // 49152 B per stage
constexpr int SMEM_BYTES = STAGES * STG;    // 147456 B -> 1 CTA / SM

// ---------------- helpers ----------------
__device__ __forceinline__ uint32_t smem_u32(const void* p) {
    return (uint32_t)__cvta_generic_to_shared(p);
}
__device__ __forceinline__ uint32_t swz(uint32_t off) {   // SW128-style XOR swizzle
    return off ^ ((off >> 3) & 0x70);
}
__device__ __forceinline__ void cp16(uint32_t dst, const void* src) {
    asm volatile("cp.async.cg.shared.global [%0], [%1], 16;\n" :: "r"(dst), "l"(src));
}
__device__ __forceinline__ void cp_commit() { asm volatile("cp.async.commit_group;\n"); }
template <int N>
__device__ __forceinline__ void cp_wait() { asm volatile("cp.async.wait_group %0;\n" :: "n"(N)); }

__device__ __forceinline__ void ldsm_x4(uint32_t* r, uint32_t addr) {
    asm volatile("ldmatrix.sync.aligned.m8n8.x4.shared.b16 {%0,%1,%2,%3}, [%4];\n"
                 : "=r"(r[0]), "=r"(r[1]), "=r"(r[2]), "=r"(r[3]) : "r"(addr));
}
__device__ __forceinline__ void mma16816(float* c, const uint32_t* a, const uint32_t* b) {
    asm volatile("mma.sync.aligned.m16n8k16.row.col.f32.f16.f16.f32 "
                 "{%0,%1,%2,%3}, {%4,%5,%6,%7}, {%8,%9}, {%0,%1,%2,%3};\n"
                 : "+f"(c[0]), "+f"(c[1]), "+f"(c[2]), "+f"(c[3])
                 : "r"(a[0]), "r"(a[1]), "r"(a[2]), "r"(a[3]), "r"(b[0]), "r"(b[1]));
}

// ---------------- fp16 GEMM:  C[M,N] = A[M,K] * W[N,K]^T + bias ----------------
// grid = (N/BN, M/BM). Grouped along M: group = bm / mRowsPerGroup.
// 8 warps, warp tile 64x64 (minimal smem traffic: 0.0625 B/MAC).
// Fine-grained pipeline: B frags double-buffered per 16-col LDSM, A per ks.
template <typename OutT>
__global__ __launch_bounds__(256, 1)
void gemm_kernel(const __half* __restrict__ A, const __half* __restrict__ W,
                 const float* __restrict__ bias, OutT* __restrict__ C,
                 int N, int K, int mRowsPerGroup) {
    extern __shared__ char smem_raw[];
    const uint32_t sbase = smem_u32(smem_raw);

    const int tid  = threadIdx.x;
    const int lane = tid & 31;
    const int warp = tid >> 5;
    const int wm   = warp & 1;    // 2 x 64 rows
    const int wn   = warp >> 1;   // 4 x 64 cols
    const int bm   = blockIdx.y * BM;
    const int bn   = blockIdx.x * BN;
    const int group = bm / mRowsPerGroup;

    const __half* gA = A + (size_t)bm * K;
    const __half* gW = W + (size_t)group * N * K + (size_t)bn * K;
    const float*  gBias = bias + (size_t)group * N + bn;
    const int kTiles = K / BK;

    // UNswizzled per-lane base offsets; all dynamic adds (ks*32, nj*2048) are
    // carry-free w.r.t. swizzle input bits [7:9], so swz(base+off) is exact.
    uint32_t aOffBase[4];
#pragma unroll
    for (int mi = 0; mi < 4; ++mi) {
        int r = wm * 64 + mi * 16 + (lane & 15);
        int c = (lane >> 4) * 8;
        aOffBase[mi] = (uint32_t)(r * 128 + c * 2);
    }
    uint32_t bOffBase;
    {
        int r = wn * 64 + ((lane >> 4) & 1) * 8 + (lane & 7);
        int c = ((lane >> 3) & 1) * 8;
        bOffBase = (uint32_t)(r * 128 + c * 2);
    }

    float acc[4][8][4];
#pragma unroll
    for (int a = 0; a < 4; a++)
#pragma unroll
        for (int b = 0; b < 8; b++)
#pragma unroll
            for (int c = 0; c < 4; c++) acc[a][b][c] = 0.f;

    auto load_stage = [&](int s, int kt) {
        const uint32_t dA = sbase + s * STG;
        const uint32_t dB = dA + ASTG;
        const __half* srcA = gA + kt * BK;
        const __half* srcB = gW + kt * BK;
#pragma unroll
        for (int i = 0; i < 4; i++) {       // A: 1024 chunks of 16B
            int q = tid + i * 256;
            int r = q >> 3, c = q & 7;
            cp16(dA + swz((uint32_t)(r * 128 + c * 16)), srcA + (size_t)r * K + c * 8);
        }
#pragma unroll
        for (int i = 0; i < 8; i++) {       // B: 2048 chunks of 16B
            int q = tid + i * 256;
            int r = q >> 3, c = q & 7;
            cp16(dB + swz((uint32_t)(r * 128 + c * 16)), srcB + (size_t)r * K + c * 8);
        }
    };

    uint32_t aF[2][4][4];     // [ks-parity][mi][frag]
    uint32_t bF[2][4];        // [step-parity][frag], one 16-col ldsm.x4
    auto load_aF = [&](int buf, uint32_t cA, int ks) {
        const uint32_t kOff = (uint32_t)(ks * 32);
#pragma unroll
        for (int mi = 0; mi < 4; ++mi)
            ldsm_x4(aF[buf][mi], cA + swz(aOffBase[mi] + kOff));
    };
    auto load_bF = [&](int buf, uint32_t cB, int ks, int nj) {
        ldsm_x4(bF[buf], cB + swz(bOffBase + (uint32_t)(nj * 2048 + ks * 32)));
    };

    // prologue: 2 stages in flight
    load_stage(0, 0); cp_commit();
    if (kTiles > 1) load_stage(1, 1);
    cp_commit();

    for (int kt = 0; kt < kTiles; ++kt) {
        cp_wait<1>();          // stage kt resident
        __syncthreads();       // all warps done with stage (kt-1)

        const uint32_t cA = sbase + (kt % STAGES) * STG;
        const uint32_t cB = cA + ASTG;

        // first fragments immediately after the barrier
        load_aF(0, cA, 0);
        load_bF(0, cB, 0, 0);

        // then issue next-stage cp.async so it overlaps all MMAs below
        const int nk = kt + 2;
        if (nk < kTiles) load_stage(nk % STAGES, nk);
        cp_commit();

        // 16 steps: t = ks*4 + nj. Per step: 1 B-ldsm prefetch (next step),
        // A-ldsm burst 2 steps before the ks boundary, then 8 MMAs.
#pragma unroll
        for (int t = 0; t < 16; ++t) {
            const int ks   = t >> 2;
            const int nj   = t & 3;
            const int acur = ks & 1;
            const int bcur = t & 1;

            if (t < 15)
                load_bF(bcur ^ 1, cB, (t + 1) >> 2, (t + 1) & 3);
            if ((t & 3) == 2 && ks < 3)
                load_aF(acur ^ 1, cA, ks + 1);

#pragma unroll
            for (int mi = 0; mi < 4; ++mi) {
                mma16816(acc[mi][2 * nj],     aF[acur][mi], &bF[bcur][0]);
                mma16816(acc[mi][2 * nj + 1], aF[acur][mi], &bF[bcur][2]);
            }
        }
    }

    // ---------------- epilogue: bias add + store ----------------
#pragma unroll
    for (int mi = 0; mi < 4; ++mi) {
#pragma unroll
        for (int ni = 0; ni < 8; ++ni) {
            int r0 = bm + wm * 64 + mi * 16 + (lane >> 2);
            int cb = wn * 64 + ni * 8 + (lane & 3) * 2;
            int c0 = bn + cb;
            float bv0 = gBias[cb], bv1 = gBias[cb + 1];
            float v0 = acc[mi][ni][0] + bv0;
            float v1 = acc[mi][ni][1] + bv1;
            float v2 = acc[mi][ni][2] + bv0;
            float v3 = acc[mi][ni][3] + bv1;
            if constexpr (sizeof(OutT) == 2) {
                *(__half2*)((__half*)C + (size_t)r0 * N + c0)       = __floats2half2_rn(v0, v1);
                *(__half2*)((__half*)C + (size_t)(r0 + 8) * N + c0) = __floats2half2_rn(v2, v3);
            } else {
                *(float2*)((float*)C + (size_t)r0 * N + c0)       = make_float2(v0, v1);
                *(float2*)((float*)C + (size_t)(r0 + 8) * N + c0) = make_float2(v2, v3);
            }
        }
    }
}

// ---------------- host launcher ----------------
static inline void* sym_addr(const void* symbol) {
    void* p = nullptr;
    cudaGetSymbolAddress(&p, symbol);
    return p;
}

extern "C" void kernel_launch(void* const* d_in, const int* in_sizes, int n_in,
                              void* d_out, int out_size) {
    const float* x    = (const float*)d_in[0];
    const float* w1   = (const float*)d_in[1];
    const float* b1   = (const float*)d_in[2];
    const float* w2   = (const float*)d_in[3];
    const float* b2   = (const float*)d_in[4];
    const float* g1w0 = (const float*)d_in[5];
    const float* g1b0 = (const float*)d_in[6];
    const float* g2w0 = (const float*)d_in[7];
    const float* g2b0 = (const float*)d_in[8];
    const float* g1w1 = (const float*)d_in[9];
    const float* g1b1 = (const float*)d_in[10];
    const float* g2w1 = (const float*)d_in[11];
    const float* g2b1 = (const float*)d_in[12];

    __half* bufA = (__half*)sym_addr(g_bufA);
    __half* bufB = (__half*)sym_addr(g_bufB);
    __half* w1h  = (__half*)sym_addr(g_w1h);
    __half* w2h  = (__half*)sym_addr(g_w2h);
    __half* l0g1 = (__half*)sym_addr(g_l0g1);
    __half* l0g2 = (__half*)sym_addr(g_l0g2);
    __half* l1g1 = (__half*)sym_addr(g_l1g1);
    __half* l1g2 = (__half*)sym_addr(g_l1g2);

    cudaFuncSetAttribute(gemm_kernel<__half>, cudaFuncAttributeMaxDynamicSharedMemorySize, SMEM_BYTES);
    cudaFuncSetAttribute(gemm_kernel<float>,  cudaFuncAttributeMaxDynamicSharedMemorySize, SMEM_BYTES);

    // ---- single fused conversion launch ----
    ConvJobs jobs;
    const float* srcs[7] = {x, w1, w2, g1w0, g2w0, g1w1, g2w1};
    __half* dsts[7]      = {bufA, w1h, w2h, l0g1, l0g2, l1g1, l1g2};
    size_t counts[7] = {(size_t)TOK * HD, (size_t)ID * HD, (size_t)HD * ID,
                        (size_t)NG * ID * HD, (size_t)NG * HD * ID,
                        (size_t)NG * ID * HD, (size_t)NG * HD * ID};
    unsigned long long acc = 0;
    for (int j = 0; j < 7; ++j) {
        jobs.src[j] = (const float4*)srcs[j];
        jobs.dst[j] = (__half2*)dsts[j];
        jobs.off[j] = acc;
        acc += counts[j] / 4;
    }
    jobs.off[7] = acc;
    {
        unsigned blocks = (unsigned)((acc + 255) / 256);
        f2h_fused_kernel<<<blocks, 256>>>(jobs);
    }

    dim3 blk(256);
    // stage 1: dense w1  [16384,2048] x [4096,2048]^T -> [16384,4096]
    gemm_kernel<__half><<<dim3(ID / BN, TOK / BM), blk, SMEM_BYTES>>>(bufA, w1h, b1, bufB, ID, HD, TOK);
    // stage 2: dense w2 -> [16384,2048]
    gemm_kernel<__half><<<dim3(HD / BN, TOK / BM), blk, SMEM_BYTES>>>(bufB, w2h, b2, bufA, HD, ID, TOK);
    // layer 0 grouped
    gemm_kernel<__half><<<dim3(ID / BN, TOK / BM), blk, SMEM_BYTES>>>(bufA, l0g1, g1b0, bufB, ID, HD, TOK / NG);
    gemm_kernel<__half><<<dim3(HD / BN, TOK / BM), blk, SMEM_BYTES>>>(bufB, l0g2, g2b0, bufA, HD, ID, TOK / NG);
    // layer 1 grouped
    gemm_kernel<__half><<<dim3(ID / BN, TOK / BM), blk, SMEM_BYTES>>>(bufA, l1g1, g1b1, bufB, ID, HD, TOK / NG);
    // final: fp32 straight to d_out
    gemm_kernel<float><<<dim3(HD / BN, TOK / BM), blk, SMEM_BYTES>>>(bufB, l1g2, g2b1, (float*)d_out, HD, ID, TOK / NG);
}

// round 13
// speedup vs baseline: 1.9737x; 1.8513x over previous
#include <cuda_runtime.h>
#include <cuda_fp16.h>
#include <cstdint>
#include <cstddef>

// ---------------- problem constants ----------------
#define TOK 16384
#define HD  2048
#define ID  4096
#define NG  4

// ---------------- device scratch ----------------
__device__ __half g_bufA[(size_t)TOK * HD];       // activations ping
__device__ __half g_bufB[(size_t)TOK * HD];       // activations pong
__device__ __half g_w2h [(size_t)HD * ID];        // w2 fp16 (straight)
__device__ __half g_w1t [(size_t)HD * ID];        // w1^T fp16 [HD][ID]
__device__ __half g_l0g2[(size_t)NG * HD * ID];   // l0 g2 fp16 straight  [G][HD][ID]
__device__ __half g_l0g1[(size_t)NG * HD * ID];   // l0 g1^T fp16 [G][HD][ID]
__device__ __half g_l1g2[(size_t)NG * HD * ID];
__device__ __half g_l1g1[(size_t)NG * HD * ID];
__device__ __half g_W12 [(size_t)HD * HD];        // combined dense weight
__device__ __half g_G12a[(size_t)NG * HD * HD];   // combined layer-0 weights
__device__ __half g_G12b[(size_t)NG * HD * HD];   // combined layer-1 weights
__device__ float  g_bd  [HD];                     // combined dense bias
__device__ float  g_bl0 [NG * HD];
__device__ float  g_bl1 [NG * HD];
__device__ float  g_zbias[NG * HD];               // zero-initialized, never written

// ---------------- fused fp32 -> fp16 straight conversion ----------------
struct ConvJobs {
    const float4* src[4];
    __half2*      dst[4];
    unsigned long long off[5];
};

__global__ __launch_bounds__(256)
void f2h_fused_kernel(ConvJobs jobs) {
    unsigned long long i = (unsigned long long)blockIdx.x * blockDim.x + threadIdx.x;
    if (i >= jobs.off[4]) return;
#pragma unroll
    for (int j = 0; j < 4; ++j) {
        if (i < jobs.off[j + 1]) {
            unsigned long long r = i - jobs.off[j];
            float4 v = jobs.src[j][r];
            jobs.dst[j][2 * r]     = __floats2half2_rn(v.x, v.y);
            jobs.dst[j][2 * r + 1] = __floats2half2_rn(v.z, v.w);
            return;
        }
    }
}

// ---------------- fp32 -> fp16 transposed conversion ----------------
// src [B][R][Cc] fp32  ->  dst [B][Cc][R] fp16
__global__ __launch_bounds__(256)
void f2h_T_kernel(const float* __restrict__ src, __half* __restrict__ dst, int R, int Cc) {
    __shared__ __half tile[32][34];
    const size_t base = (size_t)blockIdx.z * R * Cc;
    const int r0 = blockIdx.y * 32, c0 = blockIdx.x * 32;
    const int tx = threadIdx.x, ty = threadIdx.y;   // 32 x 8
#pragma unroll
    for (int i = 0; i < 32; i += 8)
        tile[ty + i][tx] = __float2half(src[base + (size_t)(r0 + ty + i) * Cc + c0 + tx]);
    __syncthreads();
#pragma unroll
    for (int i = 0; i < 32; i += 8)
        dst[base + (size_t)(c0 + ty + i) * R + r0 + tx] = tile[tx][ty + i];
}

// ---------------- combined bias: out[g][o] = sum_k W[g][o][k]*bin[g][k] + badd[g][o] ----------------
__global__ __launch_bounds__(256)
void bias_combine_kernel(const float* __restrict__ W, const float* __restrict__ bin,
                         const float* __restrict__ badd, float* __restrict__ out,
                         int OUT, int KK) {
    const int g = blockIdx.y;
    const int wpb = blockDim.x / 32;
    const int o = blockIdx.x * wpb + (threadIdx.x >> 5);
    const int lane = threadIdx.x & 31;
    if (o >= OUT) return;
    const float* wrow = W + ((size_t)g * OUT + o) * KK;
    const float* bi = bin + (size_t)g * KK;
    float s = 0.f;
    for (int k = lane; k < KK; k += 32) s += wrow[k] * bi[k];
#pragma unroll
    for (int off = 16; off; off >>= 1) s += __shfl_xor_sync(0xFFFFFFFFu, s, off);
    if (lane == 0) out[(size_t)g * OUT + o] = s + badd[(size_t)g * OUT + o];
}

// ---------------- tile config (R5 champion) ----------------
constexpr int BM = 128, BN = 128, BK = 64;
constexpr int STAGES = 3;
constexpr int ASTG = BM * 128;
constexpr int BSTG = BN * 128;
constexpr int STG  = ASTG + BSTG;           // 32768 B per stage
constexpr int SMEM_BYTES = STAGES * STG;    // 98304 B -> 2 CTAs / SM

// ---------------- helpers ----------------
__device__ __forceinline__ uint32_t smem_u32(const void* p) {
    return (uint32_t)__cvta_generic_to_shared(p);
}
__device__ __forceinline__ uint32_t swz(uint32_t off) {
    return off ^ ((off >> 3) & 0x70);
}
__device__ __forceinline__ void cp16(uint32_t dst, const void* src) {
    asm volatile("cp.async.cg.shared.global [%0], [%1], 16;\n" :: "r"(dst), "l"(src));
}
__device__ __forceinline__ void cp_commit() { asm volatile("cp.async.commit_group;\n"); }
template <int N>
__device__ __forceinline__ void cp_wait() { asm volatile("cp.async.wait_group %0;\n" :: "n"(N)); }

__device__ __forceinline__ void ldsm_x4(uint32_t* r, uint32_t addr) {
    asm volatile("ldmatrix.sync.aligned.m8n8.x4.shared.b16 {%0,%1,%2,%3}, [%4];\n"
                 : "=r"(r[0]), "=r"(r[1]), "=r"(r[2]), "=r"(r[3]) : "r"(addr));
}
__device__ __forceinline__ void mma16816(float* c, const uint32_t* a, const uint32_t* b) {
    asm volatile("mma.sync.aligned.m16n8k16.row.col.f32.f16.f16.f32 "
                 "{%0,%1,%2,%3}, {%4,%5,%6,%7}, {%8,%9}, {%0,%1,%2,%3};\n"
                 : "+f"(c[0]), "+f"(c[1]), "+f"(c[2]), "+f"(c[3])
                 : "r"(a[0]), "r"(a[1]), "r"(a[2]), "r"(a[3]), "r"(b[0]), "r"(b[1]));
}

// ---------------- fp16 GEMM:  C[M,N] = A[M,K] * W[N,K]^T + bias ----------------
// grid = (N/BN, M/BM). Grouped along M: group = bm / mRowsPerGroup.
template <typename OutT>
__global__ __launch_bounds__(256, 2)
void gemm_kernel(const __half* __restrict__ A, const __half* __restrict__ W,
                 const float* __restrict__ bias, OutT* __restrict__ C,
                 int N, int K, int mRowsPerGroup) {
    extern __shared__ char smem_raw[];
    const uint32_t sbase = smem_u32(smem_raw);

    const int tid  = threadIdx.x;
    const int lane = tid & 31;
    const int warp = tid >> 5;
    const int wm   = warp >> 2;
    const int wn   = warp & 3;
    const int bm   = blockIdx.y * BM;
    const int bn   = blockIdx.x * BN;
    const int group = bm / mRowsPerGroup;

    const __half* gA = A + (size_t)bm * K;
    const __half* gW = W + (size_t)group * N * K + (size_t)bn * K;
    const float*  gBias = bias + (size_t)group * N + bn;
    const int kTiles = K / BK;

    float acc[4][4][4];
#pragma unroll
    for (int a = 0; a < 4; a++)
#pragma unroll
        for (int b = 0; b < 4; b++)
#pragma unroll
            for (int c = 0; c < 4; c++) acc[a][b][c] = 0.f;

    auto load_stage = [&](int s, int kt) {
        const uint32_t dA = sbase + s * STG;
        const uint32_t dB = dA + ASTG;
        const __half* srcA = gA + kt * BK;
        const __half* srcB = gW + kt * BK;
#pragma unroll
        for (int i = 0; i < 4; i++) {
            int q = tid + i * 256;
            int r = q >> 3, c = q & 7;
            cp16(dA + swz((uint32_t)(r * 128 + c * 16)), srcA + (size_t)r * K + c * 8);
        }
#pragma unroll
        for (int i = 0; i < 4; i++) {
            int q = tid + i * 256;
            int r = q >> 3, c = q & 7;
            cp16(dB + swz((uint32_t)(r * 128 + c * 16)), srcB + (size_t)r * K + c * 8);
        }
    };

    load_stage(0, 0); cp_commit();
    if (kTiles > 1) load_stage(1, 1);
    cp_commit();

    for (int kt = 0; kt < kTiles; ++kt) {
        cp_wait<1>();
        __syncthreads();

        const int nk = kt + 2;
        if (nk < kTiles) load_stage(nk % STAGES, nk);
        cp_commit();

        const uint32_t cA = sbase + (kt % STAGES) * STG;
        const uint32_t cB = cA + ASTG;

#pragma unroll
        for (int ks = 0; ks < BK / 16; ++ks) {
            uint32_t aF[4][4], bF[4][2];
#pragma unroll
            for (int mi = 0; mi < 4; ++mi) {
                int r = wm * 64 + mi * 16 + (lane & 15);
                int c = ks * 16 + (lane >> 4) * 8;
                ldsm_x4(aF[mi], cA + swz((uint32_t)(r * 128 + c * 2)));
            }
#pragma unroll
            for (int np = 0; np < 2; ++np) {
                int r = wn * 32 + np * 16 + ((lane >> 4) & 1) * 8 + (lane & 7);
                int c = ks * 16 + ((lane >> 3) & 1) * 8;
                uint32_t t[4];
                ldsm_x4(t, cB + swz((uint32_t)(r * 128 + c * 2)));
                bF[2 * np][0] = t[0]; bF[2 * np][1] = t[1];
                bF[2 * np + 1][0] = t[2]; bF[2 * np + 1][1] = t[3];
            }
#pragma unroll
            for (int mi = 0; mi < 4; ++mi)
#pragma unroll
                for (int ni = 0; ni < 4; ++ni)
                    mma16816(acc[mi][ni], aF[mi], bF[ni]);
        }
    }

#pragma unroll
    for (int mi = 0; mi < 4; ++mi) {
#pragma unroll
        for (int ni = 0; ni < 4; ++ni) {
            int r0 = bm + wm * 64 + mi * 16 + (lane >> 2);
            int cb = wn * 32 + ni * 8 + (lane & 3) * 2;
            int c0 = bn + cb;
            float bv0 = gBias[cb], bv1 = gBias[cb + 1];
            float v0 = acc[mi][ni][0] + bv0;
            float v1 = acc[mi][ni][1] + bv1;
            float v2 = acc[mi][ni][2] + bv0;
            float v3 = acc[mi][ni][3] + bv1;
            if constexpr (sizeof(OutT) == 2) {
                *(__half2*)((__half*)C + (size_t)r0 * N + c0)       = __floats2half2_rn(v0, v1);
                *(__half2*)((__half*)C + (size_t)(r0 + 8) * N + c0) = __floats2half2_rn(v2, v3);
            } else {
                *(float2*)((float*)C + (size_t)r0 * N + c0)       = make_float2(v0, v1);
                *(float2*)((float*)C + (size_t)(r0 + 8) * N + c0) = make_float2(v2, v3);
            }
        }
    }
}

// ---------------- host launcher ----------------
static inline void* sym_addr(const void* symbol) {
    void* p = nullptr;
    cudaGetSymbolAddress(&p, symbol);
    return p;
}

extern "C" void kernel_launch(void* const* d_in, const int* in_sizes, int n_in,
                              void* d_out, int out_size) {
    const float* x    = (const float*)d_in[0];
    const float* w1   = (const float*)d_in[1];
    const float* b1   = (const float*)d_in[2];
    const float* w2   = (const float*)d_in[3];
    const float* b2   = (const float*)d_in[4];
    const float* g1w0 = (const float*)d_in[5];
    const float* g1b0 = (const float*)d_in[6];
    const float* g2w0 = (const float*)d_in[7];
    const float* g2b0 = (const float*)d_in[8];
    const float* g1w1 = (const float*)d_in[9];
    const float* g1b1 = (const float*)d_in[10];
    const float* g2w1 = (const float*)d_in[11];
    const float* g2b1 = (const float*)d_in[12];

    __half* bufA = (__half*)sym_addr(g_bufA);
    __half* bufB = (__half*)sym_addr(g_bufB);
    __half* w2h  = (__half*)sym_addr(g_w2h);
    __half* w1t  = (__half*)sym_addr(g_w1t);
    __half* l0g2 = (__half*)sym_addr(g_l0g2);
    __half* l0g1 = (__half*)sym_addr(g_l0g1);
    __half* l1g2 = (__half*)sym_addr(g_l1g2);
    __half* l1g1 = (__half*)sym_addr(g_l1g1);
    __half* W12  = (__half*)sym_addr(g_W12);
    __half* G12a = (__half*)sym_addr(g_G12a);
    __half* G12b = (__half*)sym_addr(g_G12b);
    float*  bd   = (float*)sym_addr(g_bd);
    float*  bl0  = (float*)sym_addr(g_bl0);
    float*  bl1  = (float*)sym_addr(g_bl1);
    float*  zb   = (float*)sym_addr(g_zbias);

    cudaFuncSetAttribute(gemm_kernel<__half>, cudaFuncAttributeMaxDynamicSharedMemorySize, SMEM_BYTES);
    cudaFuncSetAttribute(gemm_kernel<float>,  cudaFuncAttributeMaxDynamicSharedMemorySize, SMEM_BYTES);

    // ---- straight conversions: x, w2, g2w0, g2w1 ----
    ConvJobs jobs;
    const float* srcs[4] = {x, w2, g2w0, g2w1};
    __half* dsts[4]      = {bufA, w2h, l0g2, l1g2};
    size_t counts[4] = {(size_t)TOK * HD, (size_t)HD * ID,
                        (size_t)NG * HD * ID, (size_t)NG * HD * ID};
    unsigned long long acc = 0;
    for (int j = 0; j < 4; ++j) {
        jobs.src[j] = (const float4*)srcs[j];
        jobs.dst[j] = (__half2*)dsts[j];
        jobs.off[j] = acc;
        acc += counts[j] / 4;
    }
    jobs.off[4] = acc;
    f2h_fused_kernel<<<(unsigned)((acc + 255) / 256), 256>>>(jobs);

    // ---- transposed conversions: w1 -> w1t, g1w0 -> l0g1, g1w1 -> l1g1 ----
    {
        dim3 tb(32, 8);
        f2h_T_kernel<<<dim3(HD / 32, ID / 32, 1),  tb>>>(w1,   w1t,  ID, HD);
        f2h_T_kernel<<<dim3(HD / 32, ID / 32, NG), tb>>>(g1w0, l0g1, ID, HD);
        f2h_T_kernel<<<dim3(HD / 32, ID / 32, NG), tb>>>(g1w1, l1g1, ID, HD);
    }

    // ---- combined biases:  b' = W2 @ b1 + b2  (per group) ----
    {
        dim3 grid(HD / 8, 1);
        bias_combine_kernel<<<grid, 256>>>(w2, b1, b2, bd, HD, ID);
        dim3 gridg(HD / 8, NG);
        bias_combine_kernel<<<gridg, 256>>>(g2w0, g1b0, g2b0, bl0, HD, ID);
        bias_combine_kernel<<<gridg, 256>>>(g2w1, g1b1, g2b1, bl1, HD, ID);
    }

    // ---- combine GEMMs: W' = W2 * W1  (C[o][i] = sum_k w2[o,k] * w1t[i,k]) ----
    gemm_kernel<__half><<<dim3(HD / BN, HD / BM), 256, SMEM_BYTES>>>(w2h, w1t, zb, W12, HD, ID, HD);
    gemm_kernel<__half><<<dim3(HD / BN, (NG * HD) / BM), 256, SMEM_BYTES>>>(l0g2, l0g1, zb, G12a, HD, ID, HD);
    gemm_kernel<__half><<<dim3(HD / BN, (NG * HD) / BM), 256, SMEM_BYTES>>>(l1g2, l1g1, zb, G12b, HD, ID, HD);

    // ---- main passes: 3 GEMMs of [16384,2048] x [2048,2048] ----
    gemm_kernel<__half><<<dim3(HD / BN, TOK / BM), 256, SMEM_BYTES>>>(bufA, W12, bd, bufB, HD, HD, TOK);
    gemm_kernel<__half><<<dim3(HD / BN, TOK / BM), 256, SMEM_BYTES>>>(bufB, G12a, bl0, bufA, HD, HD, TOK / NG);
    gemm_kernel<float><<<dim3(HD / BN, TOK / BM), 256, SMEM_BYTES>>>(bufA, G12b, bl1, (float*)d_out, HD, HD, TOK / NG);
}